// round 5
// baseline (speedup 1.0000x reference)
#include <cuda_runtime.h>
#include <math.h>

#define T_DATA 20000
#define SUB 16
#define TNO 200
#define ENO 2000
#define INO 500
#define CHUNK 32
#define PI_F 3.14159265358979323846f

// ---------------- device scratch (no allocs allowed) ----------------
__device__ float g_syn_e[T_DATA * SUB];
__device__ float g_syn_i[T_DATA * SUB];
__device__ float g_base[T_DATA * SUB];
__device__ float g_ekT[TNO * SUB];   // [j][s]
__device__ float g_ikT[TNO * SUB];   // [j][s]
__device__ float g_hkT[TNO * SUB];   // [j][s] hist kernel
__device__ unsigned char g_seg_e[ENO];
__device__ unsigned char g_seg_i[INO];
__device__ float g_cw[SUB * SUB];    // C_den[s][q] * exp(W_spk[q]) / tau[q]
__device__ float g_rowsum[SUB];
__device__ float g_rho[SUB];
__device__ int   g_fast;

// ---------------- K0: setup ----------------
__global__ void k_setup(const float* C_den, const float* C_syn_e, const float* C_syn_i,
                        const float* Tau_e, const float* Tau_i,
                        const float* W_e, const float* W_i,
                        const float* D_e, const float* D_i,
                        const float* Tau_spk, const float* W_spk,
                        const float* W_hist, float* out_filters)
{
    int tid = threadIdx.x;
    for (int idx = tid; idx < SUB * TNO; idx += blockDim.x) {
        int s = idx / TNO, j = idx % TNO;
        float t = (float)j;
        float te  = fmaxf(t - expf(D_e[s]), 0.f);
        float tte = te / expf(Tau_e[s]);
        float ek  = tte * expf(-tte) * expf(W_e[s]);
        float ti  = fmaxf(t - expf(D_i[s]), 0.f);
        float tti = ti / expf(Tau_i[s]);
        float ik  = -tti * expf(-tti) * expf(W_i[s]);
        float tts = t / expf(Tau_spk[s]);
        float sk  = tts * expf(-tts) * expf(W_spk[s]);
        float raw = 4.0f * logf(t + 1.0f);
        float hk = 0.f;
        for (int b = 0; b < 16; b++) {
            float phi = PI_F * 0.5f * (float)b;
            float v = 0.f;
            if (!(raw < phi - PI_F || raw > phi + PI_F))
                v = 0.5f * cosf(raw - phi) + 0.5f;
            hk += W_hist[s * 16 + b] * v;
        }
        g_ekT[j * SUB + s] = ek;
        g_ikT[j * SUB + s] = ik;
        g_hkT[j * SUB + s] = hk;
        out_filters[(0  + s) * TNO + j] = ek;
        out_filters[(16 + s) * TNO + j] = ik;
        out_filters[(32 + s) * TNO + j] = sk;
        out_filters[(48 + s) * TNO + j] = hk;
    }
    for (int e = tid; e < ENO; e += blockDim.x) {
        int seg = 0;
        for (int s = 0; s < SUB; s++) if (C_syn_e[s * ENO + e] > 0.5f) seg = s;
        g_seg_e[e] = (unsigned char)seg;
    }
    for (int e = tid; e < INO; e += blockDim.x) {
        int seg = 0;
        for (int s = 0; s < SUB; s++) if (C_syn_i[s * INO + e] > 0.5f) seg = s;
        g_seg_i[e] = (unsigned char)seg;
    }
    if (tid < SUB) g_rho[tid] = expf(-1.0f / expf(Tau_spk[tid]));
    if (tid < SUB * SUB) {
        int s = tid >> 4, q = tid & 15;
        g_cw[s * SUB + q] = C_den[s * SUB + q] * expf(W_spk[q]) / expf(Tau_spk[q]);
    }
    __syncthreads();
    if (tid < SUB) {
        int s = tid;
        float rs = 0.f;
        for (int q = 0; q < SUB; q++) rs += g_cw[s * SUB + q];
        g_rowsum[s] = rs;
    }
    if (tid == 0) {
        int fast = 1;
        float r0 = g_rho[0];
        for (int s = 1; s < SUB; s++) if (g_rho[s] != r0) fast = 0;
        g_fast = fast;
    }
}

// ---------------- K1: segment sums ----------------
#define SEG_ROWS 4
__global__ void k_segsum(const float* __restrict__ S_e, const float* __restrict__ S_i)
{
    __shared__ unsigned char sege[ENO];
    __shared__ unsigned char segi[INO];
    __shared__ float acc[SEG_ROWS][32];
    int tid = threadIdx.x;
    for (int e = tid; e < ENO; e += blockDim.x) sege[e] = g_seg_e[e];
    for (int e = tid; e < INO; e += blockDim.x) segi[e] = g_seg_i[e];
    if (tid < SEG_ROWS * 32) ((float*)acc)[tid] = 0.f;
    __syncthreads();
    int t0 = blockIdx.x * SEG_ROWS;
    for (int r = 0; r < SEG_ROWS; r++) {
        const float* re = S_e + (size_t)(t0 + r) * ENO;
        for (int e = tid; e < ENO; e += blockDim.x) {
            float v = re[e];
            if (v != 0.f) atomicAdd(&acc[r][sege[e]], v);
        }
        const float* ri = S_i + (size_t)(t0 + r) * INO;
        for (int e = tid; e < INO; e += blockDim.x) {
            float v = ri[e];
            if (v != 0.f) atomicAdd(&acc[r][16 + segi[e]], v);
        }
    }
    __syncthreads();
    if (tid < SEG_ROWS * 32) {
        int r = tid >> 5, q = tid & 31;
        if (q < 16) g_syn_e[(t0 + r) * SUB + q] = acc[r][q];
        else        g_syn_i[(t0 + r) * SUB + (q - 16)] = acc[r][q];
    }
}

// ---------------- K2: causal depthwise FIR + Theta -> base ----------------
#define TILE_T 128
__global__ void k_conv(const float* __restrict__ Theta)
{
    __shared__ float se[(TILE_T + TNO) * SUB];
    __shared__ float si[(TILE_T + TNO) * SUB];
    int t0 = blockIdx.x * TILE_T;
    int tid = threadIdx.x;
    for (int idx = tid; idx < 327 * SUB; idx += blockDim.x) {
        int r = idx / SUB, s = idx % SUB;
        int tt = t0 - 200 + r;
        float ve = 0.f, vi = 0.f;
        if (tt >= 0 && tt < T_DATA) {
            ve = g_syn_e[tt * SUB + s];
            vi = g_syn_i[tt * SUB + s];
        }
        se[idx] = ve;
        si[idx] = vi;
    }
    __syncthreads();
    int s = tid & 15, tg = tid >> 4;
    float th = Theta[s];
    float acc[8];
#pragma unroll
    for (int k = 0; k < 8; k++) acc[k] = th;
    for (int j = 0; j < TNO; j++) {
        float ke = g_ekT[j * SUB + s];
        float ki = g_ikT[j * SUB + s];
#pragma unroll
        for (int k = 0; k < 8; k++) {
            int tl = tg + k * 16;
            int row = tl + 199 - j;
            acc[k] += ke * se[row * SUB + s] + ki * si[row * SUB + s];
        }
    }
#pragma unroll
    for (int k = 0; k < 8; k++) {
        int t = t0 + tg + k * 16;
        if (t < T_DATA) g_base[t * SUB + s] = acc[k];
    }
}

// ---------------- K3: chunked scan — delta-propagating fixed point ----------------
__global__ void __launch_bounds__(512, 1) k_scan(float* __restrict__ spk_out)
{
    __shared__ float k_sh[TNO * SUB];       // hist kernel [j][s]
    __shared__ unsigned ring[16 * SUB];     // spike bits: word w bit b = spike(32w+b)
    __shared__ float P_sh[CHUNK * SUB];     // pre-chunk hist contribution
    __shared__ float base_sh[CHUNK * SUB];
    __shared__ float spf[CHUNK * SUB];      // spike guess/solution (floats)
    __shared__ float inj_sh[CHUNK * SUB];   // per-step C_den injection
    __shared__ float dsh[2][CHUNK * SUB];   // delta spikes (double-buffered)
    __shared__ float dinjsh[2][CHUNK * SUB];// delta injections
    __shared__ unsigned fm[2][17];          // flip masks per s + [16]=any
    __shared__ float Kpre_sh[CHUNK * SUB];  // prefix sums of k (fallback path)
    __shared__ float Ksuf_sh[CHUNK * SUB];  // suffix sums of k (pre-phase)
    __shared__ float cw_sh[SUB * 17];
    __shared__ float rowsum_sh[SUB], rho_sh[SUB];
    __shared__ float MA0[SUB], MB0[SUB];
    __shared__ float powt[CHUNK + 1], wt[CHUNK + 1];
    __shared__ int fast_sh;

    int tid = threadIdx.x;
    for (int idx = tid; idx < TNO * SUB; idx += 512) k_sh[idx] = g_hkT[idx];
    if (tid < 256) {
        int s = tid >> 4, q = tid & 15;
        cw_sh[s * 17 + q] = g_cw[s * SUB + q];
        ring[tid] = 0u;
    }
    if (tid < SUB) {
        rowsum_sh[tid] = g_rowsum[tid];
        rho_sh[tid] = g_rho[tid];
        MA0[tid] = 0.f; MB0[tid] = 0.f;
    }
    if (tid == 0) fast_sh = g_fast;
    spf[tid] = 0.f;
    __syncthreads();
    if (tid <= CHUNK) {
        float p = powf(rho_sh[0], (float)tid);
        powt[tid] = p;
        wt[tid] = (float)tid * p;
    }
    {
        int i = tid >> 4, s = tid & 15;
        float pre = 0.f;
        for (int b = 0; b < i; b++) pre += k_sh[b * SUB + s];
        float suf = 0.f;
        for (int b = i; b < TNO; b++) suf += k_sh[b * SUB + s];
        Kpre_sh[i * SUB + s] = pre;
        Ksuf_sh[i * SUB + s] = suf;
    }
    __syncthreads();

    // fallback-path state
    float MBr = 0.f, A = 0.f, B = 0.f;
    float cwrow[16];
    if (tid < 16) {
#pragma unroll
        for (int q = 0; q < 16; q++) cwrow[q] = cw_sh[tid * 17 + q];
    }
    int i_pre = tid >> 4, s_pre = tid & 15;
    const int i = i_pre, s = s_pre;

    for (int c = 0; c < T_DATA / CHUNK; c++) {
        int t0 = c * CHUNK;
        // ---- parallel pre-phase: P[i][s] = sum over pre-chunk spikes of k[age] ----
        {
            int t = t0 + i;
            int uhi = t0 - 1;
            int ulo = t - TNO; if (ulo < 0) ulo = 0;
            float P = 0.f;
            if (uhi >= ulo) {
                int wlo = ulo >> 5;
                unsigned wv[8], vv[8];
                int ones = 0, span = 0;
#pragma unroll
                for (int q8 = 0; q8 < 8; q8++) {
                    int w = wlo + q8;
                    int bu = w << 5;
                    unsigned valid = 0u;
                    if (bu <= uhi) {
                        valid = 0xFFFFFFFFu;
                        if (bu < ulo) valid <<= (ulo - bu);
                        int hb = uhi - bu;
                        if (hb < 31) valid &= ((2u << hb) - 1u);
                    }
                    unsigned word = valid ? ring[(w & 15) * SUB + s] : 0u;
                    wv[q8] = word & valid;
                    vv[q8] = valid;
                    ones += __popc(wv[q8]);
                    span += __popc(valid);
                }
                if ((t >= TNO) && (2 * ones > span)) {
                    float acc0 = 0.f;
#pragma unroll
                    for (int q8 = 0; q8 < 8; q8++) {
                        unsigned zm = wv[q8] ^ vv[q8];
                        int Cw = t - 1 - ((wlo + q8) << 5);
                        while (zm) {
                            int b = __ffs(zm) - 1; zm &= zm - 1u;
                            acc0 += k_sh[(Cw - b) * SUB + s];
                        }
                    }
                    P = Ksuf_sh[i * SUB + s] - acc0;
                } else {
                    float acc0 = 0.f;
#pragma unroll
                    for (int q8 = 0; q8 < 8; q8++) {
                        unsigned om = wv[q8];
                        int Cw = t - 1 - ((wlo + q8) << 5);
                        while (om) {
                            int b = __ffs(om) - 1; om &= om - 1u;
                            acc0 += k_sh[(Cw - b) * SUB + s];
                        }
                    }
                    P = acc0;
                }
            }
            P_sh[tid] = P;
            base_sh[tid] = g_base[t * SUB + s];
        }
        // init injections from carried guess; clear flip masks
        {
            float iv = 0.f;
#pragma unroll
            for (int q = 0; q < 16; q++)
                iv += cw_sh[s * 17 + q] * spf[i * SUB + q];
            inj_sh[tid] = iv;
        }
        if (tid < 17) { fm[0][tid] = 0u; fm[1][tid] = 0u; }
        __syncthreads();

        if (fast_sh) {
            // ---- full evaluation of acc from the carried guess (once per chunk) ----
            float bP = base_sh[tid] + P_sh[tid]
                     + powt[i] * MB0[s] + (float)i * powt[i] * MA0[s];
            float acc = 0.f;
            for (int u = 0; u < i; u++) {
                acc += spf[u * SUB + s] * k_sh[(i - 1 - u) * SUB + s]
                     + wt[i - 1 - u] * inj_sh[u * SUB + s];
            }
            float myspf = spf[tid];
            float injv = inj_sh[tid];
            // ---- delta-propagating fixed-point iterations ----
            int pb = 0;
            for (int it = 0; it < 64; it++) {
                float sub = bP + acc;
                float ns = sub > 0.f ? 1.f : 0.f;
                float d = ns - myspf;
                int flip = (d != 0.f);
                dsh[pb][tid] = d;
                if (flip) {
                    myspf = ns;
                    atomicOr(&fm[pb][s], 1u << i);
                    atomicOr(&fm[pb][16], 1u << i);
                }
                int n = __syncthreads_count(flip);
                if (n == 0) break;
                // phase 2: delta injections for any-flip rows; clear other bank
                unsigned any = fm[pb][16];
                float dj = 0.f;
                if ((any >> i) & 1u) {
#pragma unroll
                    for (int q = 0; q < 16; q++)
                        dj += cw_sh[s * 17 + q] * dsh[pb][i * SUB + q];
                    injv += dj;
                }
                dinjsh[pb][tid] = dj;
                if (tid < 17) fm[pb ^ 1][tid] = 0u;
                __syncthreads();
                // phase 3: apply deltas to acc
                unsigned m = i ? ((1u << i) - 1u) : 0u;
                unsigned zm = fm[pb][s] & m;
                while (zm) {
                    int u = __ffs(zm) - 1; zm &= zm - 1u;
                    acc += dsh[pb][u * SUB + s] * k_sh[(i - 1 - u) * SUB + s];
                }
                unsigned am = fm[pb][16] & m;
                while (am) {
                    int u = __ffs(am) - 1; am &= am - 1u;
                    acc += wt[i - 1 - u] * dinjsh[pb][u * SUB + s];
                }
                pb ^= 1;
            }
            // publish final solution
            spf[tid] = myspf;
            inj_sh[tid] = injv;
            spk_out[t0 * SUB + tid] = myspf;
            __syncthreads();
            // epilogue: carried state + ring (closed form at i = 32)
            if (tid < 16) {
                float sA = 0.f, sB = 0.f;
                unsigned wbits = 0u;
                for (int u = 0; u < CHUNK; u++) {
                    float v = inj_sh[u * SUB + tid];
                    sA += powt[31 - u] * v;
                    sB += wt[31 - u] * v;
                    if (spf[u * SUB + tid] != 0.f) wbits |= (1u << u);
                }
                float p32 = powt[CHUNK];
                float nMA = p32 * MA0[tid] + sA;
                float nMB = p32 * MB0[tid] + 32.f * p32 * MA0[tid] + sB;
                MA0[tid] = nMA;
                MB0[tid] = nMB;
                ring[((t0 >> 5) & 15) * SUB + tid] = wbits;
            }
            __syncthreads();
        } else {
            // ---- general fallback: serial loop (non-uniform rho) ----
            if (tid < 16) {
                int ss = tid;
                unsigned myhist = 0u;
                float rho_s = rho_sh[ss];
                for (int ii = 0; ii < CHUNK; ii++) {
                    float Pv = P_sh[ii * SUB + ss];
                    float bv = base_sh[ii * SUB + ss];
                    unsigned m = ii ? ((1u << ii) - 1u) : 0u;
                    unsigned om = myhist & m;
                    float intra;
                    if (2 * __popc(om) > ii) {
                        unsigned zm = om ^ m;
                        float a = 0.f;
                        while (zm) { int b = __ffs(zm) - 1; zm &= zm - 1u; a += k_sh[b * SUB + ss]; }
                        intra = Kpre_sh[ii * SUB + ss] - a;
                    } else {
                        float a = 0.f;
                        while (om) { int b = __ffs(om) - 1; om &= om - 1u; a += k_sh[b * SUB + ss]; }
                        intra = a;
                    }
                    float sub = bv + Pv + intra + MBr;
                    bool sp = sub > 0.f;
                    spf[ii * SUB + ss] = sp ? 1.f : 0.f;
                    myhist = (myhist << 1) | (sp ? 1u : 0u);
                    float Ao = A;
                    B = rho_s * (B + Ao);
                    A = rho_s * Ao + (sp ? 1.f : 0.f);
                    float accv = 0.f;
#pragma unroll
                    for (int q = 0; q < 16; q++)
                        accv += cwrow[q] * __shfl_sync(0x0000FFFFu, B, q);
                    MBr = accv;
                }
                ring[((t0 >> 5) & 15) * SUB + ss] = __brev(myhist);
            }
            __syncthreads();
            spk_out[t0 * SUB + tid] = spf[tid];
            __syncthreads();
        }
    }
    (void)rowsum_sh;
}

// ---------------- launch ----------------
extern "C" void kernel_launch(void* const* d_in, const int* in_sizes, int n_in,
                              void* d_out, int out_size)
{
    const float* S_e     = (const float*)d_in[0];
    const float* S_i     = (const float*)d_in[1];
    const float* C_den   = (const float*)d_in[2];
    const float* C_syn_e = (const float*)d_in[3];
    const float* C_syn_i = (const float*)d_in[4];
    const float* Tau_e   = (const float*)d_in[5];
    const float* Tau_i   = (const float*)d_in[6];
    const float* W_e     = (const float*)d_in[7];
    const float* W_i     = (const float*)d_in[8];
    const float* D_e     = (const float*)d_in[9];
    const float* D_i     = (const float*)d_in[10];
    const float* Tau_spk = (const float*)d_in[11];
    const float* W_spk   = (const float*)d_in[12];
    const float* W_hist  = (const float*)d_in[13];
    const float* Theta   = (const float*)d_in[14];
    float* out = (float*)d_out;
    float* out_filters = out + T_DATA * SUB;

    k_setup<<<1, 256>>>(C_den, C_syn_e, C_syn_i, Tau_e, Tau_i, W_e, W_i,
                        D_e, D_i, Tau_spk, W_spk, W_hist, out_filters);
    k_segsum<<<T_DATA / SEG_ROWS, 256>>>(S_e, S_i);
    k_conv<<<(T_DATA + TILE_T - 1) / TILE_T, 256>>>(Theta);
    k_scan<<<1, 512>>>(out);
}

// round 6
// speedup vs baseline: 1.1199x; 1.1199x over previous
#include <cuda_runtime.h>
#include <math.h>

#define T_DATA 20000
#define SUB 16
#define TNO 200
#define ENO 2000
#define INO 500
#define CHUNK 32
#define PI_F 3.14159265358979323846f

// ---------------- device scratch (no allocs allowed) ----------------
__device__ float g_syn_e[T_DATA * SUB];
__device__ float g_syn_i[T_DATA * SUB];
__device__ float g_base[T_DATA * SUB];
__device__ float g_ekT[TNO * SUB];   // [j][s]
__device__ float g_ikT[TNO * SUB];   // [j][s]
__device__ float g_hkT[TNO * SUB];   // [j][s] hist kernel
__device__ unsigned char g_seg_e[ENO];
__device__ unsigned char g_seg_i[INO];
__device__ float g_cw[SUB * SUB];    // C_den[s][q] * exp(W_spk[q]) / tau[q]
__device__ float g_rho[SUB];
__device__ int   g_fast;

// ---------------- K0: setup ----------------
__global__ void k_setup(const float* C_den, const float* C_syn_e, const float* C_syn_i,
                        const float* Tau_e, const float* Tau_i,
                        const float* W_e, const float* W_i,
                        const float* D_e, const float* D_i,
                        const float* Tau_spk, const float* W_spk,
                        const float* W_hist, float* out_filters)
{
    int tid = threadIdx.x;
    for (int idx = tid; idx < SUB * TNO; idx += blockDim.x) {
        int s = idx / TNO, j = idx % TNO;
        float t = (float)j;
        float te  = fmaxf(t - expf(D_e[s]), 0.f);
        float tte = te / expf(Tau_e[s]);
        float ek  = tte * expf(-tte) * expf(W_e[s]);
        float ti  = fmaxf(t - expf(D_i[s]), 0.f);
        float tti = ti / expf(Tau_i[s]);
        float ik  = -tti * expf(-tti) * expf(W_i[s]);
        float tts = t / expf(Tau_spk[s]);
        float sk  = tts * expf(-tts) * expf(W_spk[s]);
        float raw = 4.0f * logf(t + 1.0f);
        float hk = 0.f;
        for (int b = 0; b < 16; b++) {
            float phi = PI_F * 0.5f * (float)b;
            float v = 0.f;
            if (!(raw < phi - PI_F || raw > phi + PI_F))
                v = 0.5f * cosf(raw - phi) + 0.5f;
            hk += W_hist[s * 16 + b] * v;
        }
        g_ekT[j * SUB + s] = ek;
        g_ikT[j * SUB + s] = ik;
        g_hkT[j * SUB + s] = hk;
        out_filters[(0  + s) * TNO + j] = ek;
        out_filters[(16 + s) * TNO + j] = ik;
        out_filters[(32 + s) * TNO + j] = sk;
        out_filters[(48 + s) * TNO + j] = hk;
    }
    for (int e = tid; e < ENO; e += blockDim.x) {
        int seg = 0;
        for (int s = 0; s < SUB; s++) if (C_syn_e[s * ENO + e] > 0.5f) seg = s;
        g_seg_e[e] = (unsigned char)seg;
    }
    for (int e = tid; e < INO; e += blockDim.x) {
        int seg = 0;
        for (int s = 0; s < SUB; s++) if (C_syn_i[s * INO + e] > 0.5f) seg = s;
        g_seg_i[e] = (unsigned char)seg;
    }
    if (tid < SUB) g_rho[tid] = expf(-1.0f / expf(Tau_spk[tid]));
    if (tid < SUB * SUB) {
        int s = tid >> 4, q = tid & 15;
        g_cw[s * SUB + q] = C_den[s * SUB + q] * expf(W_spk[q]) / expf(Tau_spk[q]);
    }
    __syncthreads();
    if (tid == 0) {
        int fast = 1;
        float r0 = g_rho[0];
        for (int s = 1; s < SUB; s++) if (g_rho[s] != r0) fast = 0;
        g_fast = fast;
    }
}

// ---------------- K1: segment sums ----------------
#define SEG_ROWS 4
__global__ void k_segsum(const float* __restrict__ S_e, const float* __restrict__ S_i)
{
    __shared__ unsigned char sege[ENO];
    __shared__ unsigned char segi[INO];
    __shared__ float acc[SEG_ROWS][32];
    int tid = threadIdx.x;
    for (int e = tid; e < ENO; e += blockDim.x) sege[e] = g_seg_e[e];
    for (int e = tid; e < INO; e += blockDim.x) segi[e] = g_seg_i[e];
    if (tid < SEG_ROWS * 32) ((float*)acc)[tid] = 0.f;
    __syncthreads();
    int t0 = blockIdx.x * SEG_ROWS;
    for (int r = 0; r < SEG_ROWS; r++) {
        const float* re = S_e + (size_t)(t0 + r) * ENO;
        for (int e = tid; e < ENO; e += blockDim.x) {
            float v = re[e];
            if (v != 0.f) atomicAdd(&acc[r][sege[e]], v);
        }
        const float* ri = S_i + (size_t)(t0 + r) * INO;
        for (int e = tid; e < INO; e += blockDim.x) {
            float v = ri[e];
            if (v != 0.f) atomicAdd(&acc[r][16 + segi[e]], v);
        }
    }
    __syncthreads();
    if (tid < SEG_ROWS * 32) {
        int r = tid >> 5, q = tid & 31;
        if (q < 16) g_syn_e[(t0 + r) * SUB + q] = acc[r][q];
        else        g_syn_i[(t0 + r) * SUB + (q - 16)] = acc[r][q];
    }
}

// ---------------- K2: causal depthwise FIR + Theta -> base ----------------
#define TILE_T 128
__global__ void k_conv(const float* __restrict__ Theta)
{
    __shared__ float se[(TILE_T + TNO) * SUB];
    __shared__ float si[(TILE_T + TNO) * SUB];
    int t0 = blockIdx.x * TILE_T;
    int tid = threadIdx.x;
    for (int idx = tid; idx < 327 * SUB; idx += blockDim.x) {
        int r = idx / SUB, s = idx % SUB;
        int tt = t0 - 200 + r;
        float ve = 0.f, vi = 0.f;
        if (tt >= 0 && tt < T_DATA) {
            ve = g_syn_e[tt * SUB + s];
            vi = g_syn_i[tt * SUB + s];
        }
        se[idx] = ve;
        si[idx] = vi;
    }
    __syncthreads();
    int s = tid & 15, tg = tid >> 4;
    float th = Theta[s];
    float acc[8];
#pragma unroll
    for (int k = 0; k < 8; k++) acc[k] = th;
    for (int j = 0; j < TNO; j++) {
        float ke = g_ekT[j * SUB + s];
        float ki = g_ikT[j * SUB + s];
#pragma unroll
        for (int k = 0; k < 8; k++) {
            int tl = tg + k * 16;
            int row = tl + 199 - j;
            acc[k] += ke * se[row * SUB + s] + ki * si[row * SUB + s];
        }
    }
#pragma unroll
    for (int k = 0; k < 8; k++) {
        int t = t0 + tg + k * 16;
        if (t < T_DATA) g_base[t * SUB + s] = acc[k];
    }
}

// ---------------- K3: chunked scan — deterministic 2-step wavefront ----------------
__global__ void __launch_bounds__(512, 1) k_scan(float* __restrict__ spk_out)
{
    __shared__ float k_sh[TNO * SUB];       // hist kernel [j][s]
    __shared__ unsigned ring[16 * SUB];     // spike bits: word w bit b = spike(32w+b)
    __shared__ float spf[CHUNK * SUB];      // resolved spikes
    __shared__ float inj_sh[CHUNK * SUB];   // per-step C_den injection
    __shared__ float P_sh[CHUNK * SUB];     // (fallback path only)
    __shared__ float base_sh[CHUNK * SUB];  // (fallback path only)
    __shared__ unsigned balw[16];           // per-round ballot words (stepA | stepB<<16)
    __shared__ float lut[4][16][16];        // nibble LUT: inj[s] from 4-bit spike groups
    __shared__ float Kpre_sh[CHUNK * SUB];  // prefix sums of k (fallback path)
    __shared__ float Ksuf_sh[CHUNK * SUB];  // suffix sums of k (pre-phase)
    __shared__ float cw_sh[SUB * 17];
    __shared__ float rho_sh[SUB];
    __shared__ float MA0[SUB], MB0[SUB];
    __shared__ float powt[CHUNK + 1], wt[CHUNK + 1];
    __shared__ float k0_sh[SUB];
    __shared__ int fast_sh;

    int tid = threadIdx.x;
    int wid = tid >> 5, lane = tid & 31;
    for (int idx = tid; idx < TNO * SUB; idx += 512) k_sh[idx] = g_hkT[idx];
    if (tid < 256) {
        int s = tid >> 4, q = tid & 15;
        cw_sh[s * 17 + q] = g_cw[s * SUB + q];
        ring[tid] = 0u;
    }
    if (tid < SUB) {
        rho_sh[tid] = g_rho[tid];
        MA0[tid] = 0.f; MB0[tid] = 0.f;
        k0_sh[tid] = g_hkT[0 * SUB + tid];
    }
    if (tid == 0) fast_sh = g_fast;
    spf[tid] = 0.f;
    __syncthreads();
    if (tid <= CHUNK) {
        float p = powf(rho_sh[0], (float)tid);
        powt[tid] = p;
        wt[tid] = (float)tid * p;
    }
    {
        int i = tid >> 4, s = tid & 15;
        float pre = 0.f;
        for (int b = 0; b < i; b++) pre += k_sh[b * SUB + s];
        float suf = 0.f;
        for (int b = i; b < TNO; b++) suf += k_sh[b * SUB + s];
        Kpre_sh[i * SUB + s] = pre;
        Ksuf_sh[i * SUB + s] = suf;
    }
    // nibble LUTs: lut[n][m][s] = sum over bits b of m of cw[s][4n+b]
    for (int idx = tid; idx < 1024; idx += 512) {
        int n = idx >> 8, m = (idx >> 4) & 15, s = idx & 15;
        float v = 0.f;
        for (int b = 0; b < 4; b++)
            if ((m >> b) & 1) v += cw_sh[s * 17 + 4 * n + b];
        lut[n][m][s] = v;
    }
    __syncthreads();

    // fallback-path state
    float MBr = 0.f, A = 0.f, B = 0.f;
    float cwrow[16];
    if (tid < 16) {
#pragma unroll
        for (int q = 0; q < 16; q++) cwrow[q] = cw_sh[tid * 17 + q];
    }
    const int i = tid >> 4, s = tid & 15;

    for (int c = 0; c < T_DATA / CHUNK; c++) {
        int t0 = c * CHUNK;
        // ---- parallel pre-phase: P = sum over pre-chunk spikes of k[age] (register) ----
        float P = 0.f;
        {
            int t = t0 + i;
            int uhi = t0 - 1;
            int ulo = t - TNO; if (ulo < 0) ulo = 0;
            if (uhi >= ulo) {
                int wlo = ulo >> 5;
                unsigned wv[8], vv[8];
                int ones = 0, span = 0;
#pragma unroll
                for (int q8 = 0; q8 < 8; q8++) {
                    int w = wlo + q8;
                    int bu = w << 5;
                    unsigned valid = 0u;
                    if (bu <= uhi) {
                        valid = 0xFFFFFFFFu;
                        if (bu < ulo) valid <<= (ulo - bu);
                        int hb = uhi - bu;
                        if (hb < 31) valid &= ((2u << hb) - 1u);
                    }
                    unsigned word = valid ? ring[(w & 15) * SUB + s] : 0u;
                    wv[q8] = word & valid;
                    vv[q8] = valid;
                    ones += __popc(wv[q8]);
                    span += __popc(valid);
                }
                if ((t >= TNO) && (2 * ones > span)) {
                    float acc0 = 0.f;
#pragma unroll
                    for (int q8 = 0; q8 < 8; q8++) {
                        unsigned zm = wv[q8] ^ vv[q8];
                        int Cw = t - 1 - ((wlo + q8) << 5);
                        while (zm) {
                            int b = __ffs(zm) - 1; zm &= zm - 1u;
                            acc0 += k_sh[(Cw - b) * SUB + s];
                        }
                    }
                    P = Ksuf_sh[i * SUB + s] - acc0;
                } else {
                    float acc0 = 0.f;
#pragma unroll
                    for (int q8 = 0; q8 < 8; q8++) {
                        unsigned om = wv[q8];
                        int Cw = t - 1 - ((wlo + q8) << 5);
                        while (om) {
                            int b = __ffs(om) - 1; om &= om - 1u;
                            acc0 += k_sh[(Cw - b) * SUB + s];
                        }
                    }
                    P = acc0;
                }
            }
        }
        float basev = g_base[(t0 + i) * SUB + s];

        if (fast_sh) {
            // bP: everything known before chunk starts
            float bP = basev + P + powt[i] * MB0[s] + (float)i * powt[i] * MA0[s];
            float acc = 0.f;
            // ---- 16 wavefront rounds, 2 steps each ----
            for (int w = 0; w < 16; w++) {
                if (wid == w) {
                    float subA = bP + acc;
                    bool pa = (lane < 16) && (subA > 0.f);
                    unsigned balA = __ballot_sync(0xFFFFFFFFu, pa) & 0xFFFFu;
                    // second step: only adjacent coupling is k[0] (wt[0] = 0)
                    float subB = subA + (((balA >> s) & 1u) ? k0_sh[s] : 0.f);
                    bool pb = (lane >= 16) && (subB > 0.f);
                    unsigned balB = __ballot_sync(0xFFFFFFFFu, pb) >> 16;
                    unsigned mybal = (lane < 16) ? balA : balB;
                    float inj = lut[0][mybal & 15][s] + lut[1][(mybal >> 4) & 15][s]
                              + lut[2][(mybal >> 8) & 15][s] + lut[3][(mybal >> 12) & 15][s];
                    int step = 2 * w + (lane >> 4);
                    inj_sh[step * SUB + s] = inj;
                    spf[step * SUB + s] = ((mybal >> s) & 1u) ? 1.f : 0.f;
                    if (lane == 0) balw[w] = balA | (balB << 16);
                }
                __syncthreads();
                int ib = 2 * w + 1;
                if (i > ib) {
                    unsigned bw = balw[w];
                    int dA = i - 1 - 2 * w, dB = dA - 1;
                    float injA = inj_sh[(2 * w) * SUB + s];
                    float injB = inj_sh[ib * SUB + s];
                    float kA = k_sh[dA * SUB + s];
                    float kB = k_sh[dB * SUB + s];
                    acc += (((bw >> s) & 1u) ? kA : 0.f)
                         + (((bw >> (16 + s)) & 1u) ? kB : 0.f)
                         + wt[dA] * injA + wt[dB] * injB;
                }
            }
            // all spf/inj final (barrier of last round)
            spk_out[t0 * SUB + tid] = spf[tid];
            // epilogue: carried state + ring (closed form at i = 32)
            if (tid < 16) {
                float sA = 0.f, sB = 0.f;
                for (int u = 0; u < CHUNK; u++) {
                    float v = inj_sh[u * SUB + tid];
                    sA += powt[31 - u] * v;
                    sB += wt[31 - u] * v;
                }
                unsigned wbits = 0u;
                for (int r = 0; r < 16; r++) {
                    unsigned bw = balw[r];
                    wbits |= ((bw >> tid) & 1u) << (2 * r);
                    wbits |= ((bw >> (16 + tid)) & 1u) << (2 * r + 1);
                }
                float p32 = powt[CHUNK];
                float nMA = p32 * MA0[tid] + sA;
                float nMB = p32 * MB0[tid] + 32.f * p32 * MA0[tid] + sB;
                MA0[tid] = nMA;
                MB0[tid] = nMB;
                ring[((t0 >> 5) & 15) * SUB + tid] = wbits;
            }
            __syncthreads();
        } else {
            // ---- general fallback: serial loop (non-uniform rho) ----
            P_sh[tid] = P;
            base_sh[tid] = basev;
            __syncthreads();
            if (tid < 16) {
                int ss = tid;
                unsigned myhist = 0u;
                float rho_s = rho_sh[ss];
                for (int ii = 0; ii < CHUNK; ii++) {
                    float Pv = P_sh[ii * SUB + ss];
                    float bv = base_sh[ii * SUB + ss];
                    unsigned m = ii ? ((1u << ii) - 1u) : 0u;
                    unsigned om = myhist & m;
                    float intra;
                    if (2 * __popc(om) > ii) {
                        unsigned zm = om ^ m;
                        float a = 0.f;
                        while (zm) { int b = __ffs(zm) - 1; zm &= zm - 1u; a += k_sh[b * SUB + ss]; }
                        intra = Kpre_sh[ii * SUB + ss] - a;
                    } else {
                        float a = 0.f;
                        while (om) { int b = __ffs(om) - 1; om &= om - 1u; a += k_sh[b * SUB + ss]; }
                        intra = a;
                    }
                    float sub = bv + Pv + intra + MBr;
                    bool sp = sub > 0.f;
                    spf[ii * SUB + ss] = sp ? 1.f : 0.f;
                    myhist = (myhist << 1) | (sp ? 1u : 0u);
                    float Ao = A;
                    B = rho_s * (B + Ao);
                    A = rho_s * Ao + (sp ? 1.f : 0.f);
                    float accv = 0.f;
#pragma unroll
                    for (int q = 0; q < 16; q++)
                        accv += cwrow[q] * __shfl_sync(0x0000FFFFu, B, q);
                    MBr = accv;
                }
                ring[((t0 >> 5) & 15) * SUB + ss] = __brev(myhist);
            }
            __syncthreads();
            spk_out[t0 * SUB + tid] = spf[tid];
            __syncthreads();
        }
    }
}

// ---------------- launch ----------------
extern "C" void kernel_launch(void* const* d_in, const int* in_sizes, int n_in,
                              void* d_out, int out_size)
{
    const float* S_e     = (const float*)d_in[0];
    const float* S_i     = (const float*)d_in[1];
    const float* C_den   = (const float*)d_in[2];
    const float* C_syn_e = (const float*)d_in[3];
    const float* C_syn_i = (const float*)d_in[4];
    const float* Tau_e   = (const float*)d_in[5];
    const float* Tau_i   = (const float*)d_in[6];
    const float* W_e     = (const float*)d_in[7];
    const float* W_i     = (const float*)d_in[8];
    const float* D_e     = (const float*)d_in[9];
    const float* D_i     = (const float*)d_in[10];
    const float* Tau_spk = (const float*)d_in[11];
    const float* W_spk   = (const float*)d_in[12];
    const float* W_hist  = (const float*)d_in[13];
    const float* Theta   = (const float*)d_in[14];
    float* out = (float*)d_out;
    float* out_filters = out + T_DATA * SUB;

    k_setup<<<1, 256>>>(C_den, C_syn_e, C_syn_i, Tau_e, Tau_i, W_e, W_i,
                        D_e, D_i, Tau_spk, W_spk, W_hist, out_filters);
    k_segsum<<<T_DATA / SEG_ROWS, 256>>>(S_e, S_i);
    k_conv<<<(T_DATA + TILE_T - 1) / TILE_T, 256>>>(Theta);
    k_scan<<<1, 512>>>(out);
}